// round 9
// baseline (speedup 1.0000x reference)
#include <cuda_runtime.h>
#include <cuda_bf16.h>
#include <cstdint>

// Problem constants: B=4, N=256, D=128, M=128, C=128
#define BB 4
#define NN 256
#define DD 128
#define MM 128
#define CC 128
#define TJ 32
#define NTILES (NN / TJ)   // 8

// Scratch (device globals — no allocation allowed)
// g_pi/g_pjb PRE-SCALED by 0.5 so hx = g_pi + g_pjb = pre/2; silu(pre)=hx+hx*tanh(hx)
__device__ float g_pi[BB * NN * MM];
__device__ float g_pjb[BB * NN * MM];
__device__ float g_W2cT[MM * MM];   // (W2 @ Wc1)^T : [col][m]
__device__ float g_Wc2T[CC * MM];   // Wc2^T        : [c][m]
__device__ float g_b2c[MM];         // b2 @ Wc1

__device__ __forceinline__ float tanh_approx(float x) {
    float y;
    asm("tanh.approx.f32 %0, %1;" : "=f"(y) : "f"(x));
    return y;
}
__device__ __forceinline__ float siluf(float x) {
    return __fdividef(x, 1.0f + __expf(-x));
}
__device__ __forceinline__ void cp16(unsigned int dst, const float* src) {
    asm volatile("cp.async.cg.shared.global [%0], [%1], 16;" :: "r"(dst), "l"(src));
}
#define CP_COMMIT()   asm volatile("cp.async.commit_group;")
#define CP_WAIT(n)    asm volatile("cp.async.wait_group %0;" :: "n"(n))

// ---------------------------------------------------------------------------
// Prep kernel: 337 blocks x 256 threads.
//  [0,256):   projection (4 rows per block)
//  [256,320): W2cT = (W2 @ Wc1)^T, 2 m-rows per block
//  [320,336): Wc2T transpose, 8 cols per block
//  336:       b2c = b2 @ Wc1
// ---------------------------------------------------------------------------
__global__ void __launch_bounds__(256) prep_kernel(
    const float* __restrict__ h,
    const float* __restrict__ W1a,
    const float* __restrict__ W1b,
    const float* __restrict__ b1,
    const float* __restrict__ W2,
    const float* __restrict__ b2,
    const float* __restrict__ Wc1,
    const float* __restrict__ Wc2)
{
    const int t = threadIdx.x;

    if (blockIdx.x < 256) {
        const int row0 = blockIdx.x * 4;
        const int col  = t & 127;
        const int rh   = (t >> 7) * 2;

        __shared__ float hsh[4][DD];
        #pragma unroll
        for (int k = 0; k < 2; k++) {
            int idx = k * 256 + t;
            hsh[idx >> 7][idx & 127] = h[(size_t)row0 * DD + idx];
        }
        __syncthreads();

        float a0 = 0.f, a1 = 0.f, p0 = 0.f, p1 = 0.f;
        #pragma unroll 8
        for (int d = 0; d < DD; d++) {
            const float wa = W1a[d * MM + col];
            const float wb = W1b[d * MM + col];
            const float h0 = hsh[rh][d];
            const float h1 = hsh[rh + 1][d];
            a0 = fmaf(h0, wa, a0);
            a1 = fmaf(h1, wa, a1);
            p0 = fmaf(h0, wb, p0);
            p1 = fmaf(h1, wb, p1);
        }
        const float bb = b1[col];
        const int r0 = row0 + rh;
        g_pi[(size_t)r0 * MM + col]        = 0.5f * a0;
        g_pi[(size_t)(r0 + 1) * MM + col]  = 0.5f * a1;
        g_pjb[(size_t)r0 * MM + col]       = 0.5f * (p0 + bb);
        g_pjb[(size_t)(r0 + 1) * MM + col] = 0.5f * (p1 + bb);
    } else if (blockIdx.x < 320) {
        const int m  = (blockIdx.x - 256) * 2 + (t >> 7);
        const int k  = t & 127;

        __shared__ float w2row[2][MM];
        w2row[t >> 7][k] = W2[m * MM + k];
        __syncthreads();

        float v0 = 0.f, v1 = 0.f;
        #pragma unroll 8
        for (int l = 0; l < MM; l += 2) {
            v0 = fmaf(w2row[t >> 7][l],     Wc1[l * MM + k],       v0);
            v1 = fmaf(w2row[t >> 7][l + 1], Wc1[(l + 1) * MM + k], v1);
        }
        g_W2cT[k * MM + m] = v0 + v1;            // transposed store
    } else if (blockIdx.x < 336) {
        // Wc2T[c][m] = Wc2[m][c]
        const int c  = (blockIdx.x - 320) * 8 + (t >> 5);
        const int m4 = (t & 31) * 4;
        float4 v;
        v.x = Wc2[(m4 + 0) * CC + c];
        v.y = Wc2[(m4 + 1) * CC + c];
        v.z = Wc2[(m4 + 2) * CC + c];
        v.w = Wc2[(m4 + 3) * CC + c];
        *reinterpret_cast<float4*>(g_Wc2T + (size_t)c * MM + m4) = v;
    } else {
        if (t < MM) {
            float v = 0.f;
            #pragma unroll 8
            for (int l = 0; l < MM; l++)
                v = fmaf(b2[l], Wc1[l * MM + t], v);
            g_b2c[t] = v;
        }
    }
}

// ---------------------------------------------------------------------------
// Main kernel: one block per (b, i0..i0+1). 256 threads = 8 warps.
// j processed in 8 tiles of 32 rows, block-wide cp.async double buffer.
// Each tile is consumed for BOTH i's (2x data reuse).
// Warp w handles rows {w, w+8, w+16, w+24} of each tile; lane = m-quad.
// ---------------------------------------------------------------------------
__global__ void __launch_bounds__(256) main_kernel(
    const float* __restrict__ adj,
    const float* __restrict__ bc1,
    const float* __restrict__ bc2,
    float* __restrict__ out)
{
    const int bi2 = blockIdx.x;         // 0..511
    const int b   = bi2 >> 7;
    const int i0  = (bi2 & 127) * 2;
    const int t   = threadIdx.x;
    const int lane = t & 31;
    const int w    = t >> 5;

    __shared__ float4 ring[2][TJ][32];  // 32KB: buf, row, m-quad
    __shared__ float adjsh[2][NN];
    __shared__ float accsh[8][2][MM];
    __shared__ float wsum[2][8];
    __shared__ float sacc[2][MM];
    __shared__ float shid[2][MM];

    // adj rows for both i's; fold diagonal mask; reduce sums
    const float* arow0 = adj + ((size_t)(b * NN + i0)) * NN;
    const float* arow1 = arow0 + NN;
    float a0 = arow0[t], a1 = arow1[t];
    adjsh[0][t] = (t == i0)     ? 0.0f : a0;
    adjsh[1][t] = (t == i0 + 1) ? 0.0f : a1;
    const float ii0 = arow0[i0];
    const float ii1 = arow1[i0 + 1];
    #pragma unroll
    for (int o = 16; o; o >>= 1) {
        a0 += __shfl_xor_sync(0xFFFFFFFFu, a0, o);
        a1 += __shfl_xor_sync(0xFFFFFFFFu, a1, o);
    }
    if (lane == 0) { wsum[0][w] = a0; wsum[1][w] = a1; }
    __syncthreads();

    float sum0 = 0.f, sum1 = 0.f;
    #pragma unroll
    for (int g = 0; g < 8; g++) { sum0 += wsum[0][g]; sum1 += wsum[1][g]; }
    const float S0   = sum0 - ii0;
    const float S1   = sum1 - ii1;
    const float inv0 = __fdividef(1.0f, fmaxf(sum0, 1.0f));
    const float inv1 = __fdividef(1.0f, fmaxf(sum1, 1.0f));

    const float4 piA = *reinterpret_cast<const float4*>(
        g_pi + ((size_t)(b * NN + i0)) * MM + lane * 4);
    const float4 piB = *reinterpret_cast<const float4*>(
        g_pi + ((size_t)(b * NN + i0 + 1)) * MM + lane * 4);
    const float* pjb_b = g_pjb + (size_t)b * NN * MM;

    const unsigned int ring_u =
        (unsigned int)__cvta_generic_to_shared(&ring[0][0][0]);

    // Prologue: tile 0
    #pragma unroll
    for (int q = 0; q < 4; q++) {
        const int idx = q * 256 + t;                 // 0..1023 float4s
        cp16(ring_u + idx * 16, pjb_b + idx * 4);
    }
    CP_COMMIT();

    float4 accA = make_float4(0.f, 0.f, 0.f, 0.f);
    float4 accB = make_float4(0.f, 0.f, 0.f, 0.f);

    #pragma unroll
    for (int jt = 0; jt < NTILES; jt++) {
        if (jt + 1 < NTILES) {
            const unsigned int dst = ring_u + ((jt + 1) & 1) * (TJ * 32 * 16);
            const float* src = pjb_b + (size_t)(jt + 1) * TJ * MM;
            #pragma unroll
            for (int q = 0; q < 4; q++) {
                const int idx = q * 256 + t;
                cp16(dst + idx * 16, src + idx * 4);
            }
            CP_COMMIT();
            CP_WAIT(1);
        } else {
            CP_WAIT(0);
        }
        __syncthreads();

        const float4* buf = &ring[jt & 1][0][0];
        #pragma unroll
        for (int rr = 0; rr < 4; rr++) {
            const int row = w + rr * 8;
            const float4 v = buf[row * 32 + lane];
            const int j = jt * TJ + row;
            const float w0 = adjsh[0][j];
            const float w1 = adjsh[1][j];
            // i = i0
            {
                float hx0 = piA.x + v.x, hx1 = piA.y + v.y;
                float hx2 = piA.z + v.z, hx3 = piA.w + v.w;
                float s0 = fmaf(hx0, tanh_approx(hx0), hx0);
                float s1 = fmaf(hx1, tanh_approx(hx1), hx1);
                float s2 = fmaf(hx2, tanh_approx(hx2), hx2);
                float s3 = fmaf(hx3, tanh_approx(hx3), hx3);
                accA.x = fmaf(w0, s0, accA.x);
                accA.y = fmaf(w0, s1, accA.y);
                accA.z = fmaf(w0, s2, accA.z);
                accA.w = fmaf(w0, s3, accA.w);
            }
            // i = i0+1
            {
                float hx0 = piB.x + v.x, hx1 = piB.y + v.y;
                float hx2 = piB.z + v.z, hx3 = piB.w + v.w;
                float s0 = fmaf(hx0, tanh_approx(hx0), hx0);
                float s1 = fmaf(hx1, tanh_approx(hx1), hx1);
                float s2 = fmaf(hx2, tanh_approx(hx2), hx2);
                float s3 = fmaf(hx3, tanh_approx(hx3), hx3);
                accB.x = fmaf(w1, s0, accB.x);
                accB.y = fmaf(w1, s1, accB.y);
                accB.z = fmaf(w1, s2, accB.z);
                accB.w = fmaf(w1, s3, accB.w);
            }
        }
        __syncthreads();
    }

    *reinterpret_cast<float4*>(&accsh[w][0][lane * 4]) = accA;
    *reinterpret_cast<float4*>(&accsh[w][1][lane * 4]) = accB;
    __syncthreads();

    // Reduce across warps: thread -> (ii = t>>7, m = t&127)
    const int ii  = t >> 7;
    const int col = t & 127;
    {
        float v = 0.f;
        #pragma unroll
        for (int g = 0; g < 8; g++) v += accsh[g][ii][col];
        sacc[ii][col] = v;
    }
    __syncthreads();

    const float Si   = ii ? S1 : S0;
    const float invi = ii ? inv1 : inv0;

    // Stage 1: hid = silu((sacc @ W2c + S*b2c)*inv_d + bc1), via transposed W2cT
    {
        const float4* s4 = reinterpret_cast<const float4*>(&sacc[ii][0]);
        const float4* w4 = reinterpret_cast<const float4*>(g_W2cT + (size_t)col * MM);
        float v0 = 0.f, v1 = 0.f, v2 = 0.f, v3 = 0.f;
        #pragma unroll 8
        for (int q = 0; q < 32; q++) {
            const float4 a = s4[q];
            const float4 wv = w4[q];
            v0 = fmaf(a.x, wv.x, v0);
            v1 = fmaf(a.y, wv.y, v1);
            v2 = fmaf(a.z, wv.z, v2);
            v3 = fmaf(a.w, wv.w, v3);
        }
        const float u = fmaf((v0 + v1) + (v2 + v3) + Si * g_b2c[col], invi, bc1[col]);
        shid[ii][col] = siluf(u);
    }
    __syncthreads();

    // Stage 2: out = hid @ Wc2 + bc2, via transposed Wc2T
    {
        const float4* h4 = reinterpret_cast<const float4*>(&shid[ii][0]);
        const float4* w4 = reinterpret_cast<const float4*>(g_Wc2T + (size_t)col * MM);
        float v0 = 0.f, v1 = 0.f, v2 = 0.f, v3 = 0.f;
        #pragma unroll 8
        for (int q = 0; q < 32; q++) {
            const float4 a = h4[q];
            const float4 wv = w4[q];
            v0 = fmaf(a.x, wv.x, v0);
            v1 = fmaf(a.y, wv.y, v1);
            v2 = fmaf(a.z, wv.z, v2);
            v3 = fmaf(a.w, wv.w, v3);
        }
        out[((size_t)(b * NN + i0 + ii)) * CC + col] =
            (v0 + v1) + (v2 + v3) + bc2[col];
    }
}

// ---------------------------------------------------------------------------
// Launch
// ---------------------------------------------------------------------------
extern "C" void kernel_launch(void* const* d_in, const int* in_sizes, int n_in,
                              void* d_out, int out_size)
{
    const float* h   = (const float*)d_in[0];
    const float* adj = (const float*)d_in[1];
    const float* W1a = (const float*)d_in[2];
    const float* W1b = (const float*)d_in[3];
    const float* b1  = (const float*)d_in[4];
    const float* W2  = (const float*)d_in[5];
    const float* b2  = (const float*)d_in[6];
    const float* Wc1 = (const float*)d_in[7];
    const float* bc1 = (const float*)d_in[8];
    const float* Wc2 = (const float*)d_in[9];
    const float* bc2 = (const float*)d_in[10];
    float* out = (float*)d_out;

    prep_kernel<<<337, 256>>>(h, W1a, W1b, b1, W2, b2, Wc1, Wc2);
    main_kernel<<<BB * NN / 2, 256>>>(adj, bc1, bc2, out);
}

// round 10
// speedup vs baseline: 1.7517x; 1.7517x over previous
#include <cuda_runtime.h>
#include <cuda_bf16.h>
#include <cstdint>

// Problem constants: B=4, N=256, D=128, M=128, C=128
#define BB 4
#define NN 256
#define DD 128
#define MM 128
#define CC 128

// Scratch (device globals — no allocation allowed)
// g_pi/g_pjb PRE-SCALED by 0.5 so hx = g_pi + g_pjb = pre/2; silu(pre)=hx+hx*tanh(hx)
__device__ float g_pi[BB * NN * MM];
__device__ float g_pjb[BB * NN * MM];
__device__ float g_W2c[MM * MM];   // W2 @ Wc1
__device__ float g_b2c[MM];        // b2 @ Wc1

__device__ __forceinline__ float tanh_approx(float x) {
    float y;
    asm("tanh.approx.f32 %0, %1;" : "=f"(y) : "f"(x));
    return y;
}
__device__ __forceinline__ float siluf(float x) {
    return __fdividef(x, 1.0f + __expf(-x));
}
__device__ __forceinline__ void cp16(unsigned int dst, const float* src) {
    asm volatile("cp.async.cg.shared.global [%0], [%1], 16;" :: "r"(dst), "l"(src));
}
#define CP_COMMIT()   asm volatile("cp.async.commit_group;")
#define CP_WAIT(n)    asm volatile("cp.async.wait_group %0;" :: "n"(n))

// ---------------------------------------------------------------------------
// Prep kernel: 321 blocks x 256 threads (same as R8 — known good).
// ---------------------------------------------------------------------------
__global__ void __launch_bounds__(256) prep_kernel(
    const float* __restrict__ h,
    const float* __restrict__ W1a,
    const float* __restrict__ W1b,
    const float* __restrict__ b1,
    const float* __restrict__ W2,
    const float* __restrict__ b2,
    const float* __restrict__ Wc1)
{
    const int t = threadIdx.x;

    if (blockIdx.x < 256) {
        const int row0 = blockIdx.x * 4;
        const int col  = t & 127;
        const int rh   = (t >> 7) * 2;

        __shared__ float hsh[4][DD];
        #pragma unroll
        for (int k = 0; k < 2; k++) {
            int idx = k * 256 + t;
            hsh[idx >> 7][idx & 127] = h[(size_t)row0 * DD + idx];
        }
        __syncthreads();

        float a0 = 0.f, a1 = 0.f, p0 = 0.f, p1 = 0.f;
        #pragma unroll 8
        for (int d = 0; d < DD; d++) {
            const float wa = W1a[d * MM + col];
            const float wb = W1b[d * MM + col];
            const float h0 = hsh[rh][d];
            const float h1 = hsh[rh + 1][d];
            a0 = fmaf(h0, wa, a0);
            a1 = fmaf(h1, wa, a1);
            p0 = fmaf(h0, wb, p0);
            p1 = fmaf(h1, wb, p1);
        }
        const float bb = b1[col];
        const int r0 = row0 + rh;
        g_pi[(size_t)r0 * MM + col]        = 0.5f * a0;
        g_pi[(size_t)(r0 + 1) * MM + col]  = 0.5f * a1;
        g_pjb[(size_t)r0 * MM + col]       = 0.5f * (p0 + bb);
        g_pjb[(size_t)(r0 + 1) * MM + col] = 0.5f * (p1 + bb);
    } else if (blockIdx.x < 320) {
        const int m  = (blockIdx.x - 256) * 2 + (t >> 7);
        const int k  = t & 127;

        __shared__ float w2row[2][MM];
        w2row[t >> 7][k] = W2[m * MM + k];
        __syncthreads();

        float v0 = 0.f, v1 = 0.f;
        #pragma unroll 8
        for (int l = 0; l < MM; l += 2) {
            v0 = fmaf(w2row[t >> 7][l],     Wc1[l * MM + k],       v0);
            v1 = fmaf(w2row[t >> 7][l + 1], Wc1[(l + 1) * MM + k], v1);
        }
        g_W2c[m * MM + k] = v0 + v1;
    } else {
        if (t < MM) {
            float v = 0.f;
            #pragma unroll 8
            for (int l = 0; l < MM; l++)
                v = fmaf(b2[l], Wc1[l * MM + t], v);
            g_b2c[t] = v;
        }
    }
}

// ---------------------------------------------------------------------------
// Main kernel: one block per (b, i0..i0+1). 256 threads = 8 warps.
// Per-warp cp.async ring exactly like R8 (6 slots, distance 4, fully
// unrolled, NO mainloop barriers). Each loaded pjb row feeds BOTH i's.
// ---------------------------------------------------------------------------
__global__ void __launch_bounds__(256) main_kernel(
    const float* __restrict__ adj,
    const float* __restrict__ bc1,
    const float* __restrict__ Wc2,
    const float* __restrict__ bc2,
    float* __restrict__ out)
{
    const int bi2 = blockIdx.x;         // 0..511
    const int b   = bi2 >> 7;
    const int i0  = (bi2 & 127) * 2;
    const int t   = threadIdx.x;
    const int lane = t & 31;
    const int w    = t >> 5;

    __shared__ float4 ring[8][6][32];   // 24KB: warp, slot, m-quad
    __shared__ float adjsh[2][NN];
    __shared__ float accsh[8][2][MM];   // 8KB
    __shared__ float wsum[2][8];
    __shared__ float sacc[2][MM];
    __shared__ float shid[2][MM];

    // adj rows for both i's; fold diagonal mask; reduce sums
    const float* arow0 = adj + ((size_t)(b * NN + i0)) * NN;
    const float* arow1 = arow0 + NN;
    float a0 = arow0[t], a1 = arow1[t];
    adjsh[0][t] = (t == i0)     ? 0.0f : a0;
    adjsh[1][t] = (t == i0 + 1) ? 0.0f : a1;
    const float ii0 = arow0[i0];
    const float ii1 = arow1[i0 + 1];
    #pragma unroll
    for (int o = 16; o; o >>= 1) {
        a0 += __shfl_xor_sync(0xFFFFFFFFu, a0, o);
        a1 += __shfl_xor_sync(0xFFFFFFFFu, a1, o);
    }
    if (lane == 0) { wsum[0][w] = a0; wsum[1][w] = a1; }
    __syncthreads();

    float sum0 = 0.f, sum1 = 0.f;
    #pragma unroll
    for (int g = 0; g < 8; g++) { sum0 += wsum[0][g]; sum1 += wsum[1][g]; }
    const float S0   = sum0 - ii0;
    const float S1   = sum1 - ii1;
    const float inv0 = __fdividef(1.0f, fmaxf(sum0, 1.0f));
    const float inv1 = __fdividef(1.0f, fmaxf(sum1, 1.0f));

    const float4 piA = *reinterpret_cast<const float4*>(
        g_pi + ((size_t)(b * NN + i0)) * MM + lane * 4);
    const float4 piB = *reinterpret_cast<const float4*>(
        g_pi + ((size_t)(b * NN + i0 + 1)) * MM + lane * 4);

    // warp w's rows: j = w + 8*jo; each lane copies 16B at lane*4 floats
    const float* base = g_pjb + (size_t)b * NN * MM + (size_t)w * MM + lane * 4;

    const unsigned int ring_lane =
        (unsigned int)__cvta_generic_to_shared(&ring[w][0][lane]);
    const float4* ring_rd = &ring[w][0][lane];   // slot stride = 32 float4
    const float*  adjA = adjsh[0] + w;           // weight at adjA[8*jo]
    const float*  adjB = adjsh[1] + w;

    float4 accA = make_float4(0.f, 0.f, 0.f, 0.f);
    float4 accB = make_float4(0.f, 0.f, 0.f, 0.f);

    // Prologue: 4 rows in flight (rows jo = 0..3)
    #pragma unroll
    for (int r = 0; r < 4; r++) {
        cp16(ring_lane + (unsigned int)(r * 32 * sizeof(float4)), base + 8 * r * MM);
        CP_COMMIT();
    }

    // Steady state: FULLY unrolled; slot = jo%6, all offsets immediates
    #pragma unroll
    for (int jo = 0; jo < 28; jo++) {
        CP_WAIT(3);
        const float4 v = ring_rd[(jo % 6) * 32];
        const float w0 = adjA[8 * jo];
        const float w1 = adjB[8 * jo];
        {
            float hx0 = piA.x + v.x, hx1 = piA.y + v.y;
            float hx2 = piA.z + v.z, hx3 = piA.w + v.w;
            float s0 = fmaf(hx0, tanh_approx(hx0), hx0);
            float s1 = fmaf(hx1, tanh_approx(hx1), hx1);
            float s2 = fmaf(hx2, tanh_approx(hx2), hx2);
            float s3 = fmaf(hx3, tanh_approx(hx3), hx3);
            accA.x = fmaf(w0, s0, accA.x);
            accA.y = fmaf(w0, s1, accA.y);
            accA.z = fmaf(w0, s2, accA.z);
            accA.w = fmaf(w0, s3, accA.w);
        }
        {
            float hx0 = piB.x + v.x, hx1 = piB.y + v.y;
            float hx2 = piB.z + v.z, hx3 = piB.w + v.w;
            float s0 = fmaf(hx0, tanh_approx(hx0), hx0);
            float s1 = fmaf(hx1, tanh_approx(hx1), hx1);
            float s2 = fmaf(hx2, tanh_approx(hx2), hx2);
            float s3 = fmaf(hx3, tanh_approx(hx3), hx3);
            accB.x = fmaf(w1, s0, accB.x);
            accB.y = fmaf(w1, s1, accB.y);
            accB.z = fmaf(w1, s2, accB.z);
            accB.w = fmaf(w1, s3, accB.w);
        }
        // issue row jo+4 into slot (jo+4)%6
        cp16(ring_lane + (unsigned int)(((jo + 4) % 6) * 32 * sizeof(float4)),
             base + 8 * (jo + 4) * MM);
        CP_COMMIT();
    }

    // Drain: consume rows 28..31
    CP_WAIT(0);
    #pragma unroll
    for (int jo = 28; jo < 32; jo++) {
        const float4 v = ring_rd[(jo % 6) * 32];
        const float w0 = adjA[8 * jo];
        const float w1 = adjB[8 * jo];
        {
            float hx0 = piA.x + v.x, hx1 = piA.y + v.y;
            float hx2 = piA.z + v.z, hx3 = piA.w + v.w;
            float s0 = fmaf(hx0, tanh_approx(hx0), hx0);
            float s1 = fmaf(hx1, tanh_approx(hx1), hx1);
            float s2 = fmaf(hx2, tanh_approx(hx2), hx2);
            float s3 = fmaf(hx3, tanh_approx(hx3), hx3);
            accA.x = fmaf(w0, s0, accA.x);
            accA.y = fmaf(w0, s1, accA.y);
            accA.z = fmaf(w0, s2, accA.z);
            accA.w = fmaf(w0, s3, accA.w);
        }
        {
            float hx0 = piB.x + v.x, hx1 = piB.y + v.y;
            float hx2 = piB.z + v.z, hx3 = piB.w + v.w;
            float s0 = fmaf(hx0, tanh_approx(hx0), hx0);
            float s1 = fmaf(hx1, tanh_approx(hx1), hx1);
            float s2 = fmaf(hx2, tanh_approx(hx2), hx2);
            float s3 = fmaf(hx3, tanh_approx(hx3), hx3);
            accB.x = fmaf(w1, s0, accB.x);
            accB.y = fmaf(w1, s1, accB.y);
            accB.z = fmaf(w1, s2, accB.z);
            accB.w = fmaf(w1, s3, accB.w);
        }
    }

    *reinterpret_cast<float4*>(&accsh[w][0][lane * 4]) = accA;
    *reinterpret_cast<float4*>(&accsh[w][1][lane * 4]) = accB;
    __syncthreads();

    // Reduce across warps: thread -> (ii = t>>7, col = t&127)
    const int ii  = t >> 7;
    const int col = t & 127;
    {
        float v = 0.f;
        #pragma unroll
        for (int g = 0; g < 8; g++) v += accsh[g][ii][col];
        sacc[ii][col] = v;
    }
    __syncthreads();

    const float Si   = ii ? S1 : S0;
    const float invi = ii ? inv1 : inv0;

    // Stage 1: hid = silu((sacc @ W2c + S*b2c)*inv_d + bc1)
    // Coalesced: threads in a warp read consecutive cols of W2c.
    {
        const float* s = sacc[ii];
        float v0 = 0.f, v1 = 0.f, v2 = 0.f, v3 = 0.f;
        #pragma unroll 8
        for (int m2 = 0; m2 < MM; m2 += 4) {
            v0 = fmaf(s[m2],     g_W2c[m2 * MM + col],       v0);
            v1 = fmaf(s[m2 + 1], g_W2c[(m2 + 1) * MM + col], v1);
            v2 = fmaf(s[m2 + 2], g_W2c[(m2 + 2) * MM + col], v2);
            v3 = fmaf(s[m2 + 3], g_W2c[(m2 + 3) * MM + col], v3);
        }
        const float u = fmaf((v0 + v1) + (v2 + v3) + Si * g_b2c[col], invi, bc1[col]);
        shid[ii][col] = siluf(u);
    }
    __syncthreads();

    // Stage 2: out = hid @ Wc2 + bc2 (coalesced)
    {
        const float* hd = shid[ii];
        float v0 = bc2[col], v1 = 0.f, v2 = 0.f, v3 = 0.f;
        #pragma unroll 8
        for (int m2 = 0; m2 < MM; m2 += 4) {
            v0 = fmaf(hd[m2],     Wc2[m2 * CC + col],       v0);
            v1 = fmaf(hd[m2 + 1], Wc2[(m2 + 1) * CC + col], v1);
            v2 = fmaf(hd[m2 + 2], Wc2[(m2 + 2) * CC + col], v2);
            v3 = fmaf(hd[m2 + 3], Wc2[(m2 + 3) * CC + col], v3);
        }
        out[((size_t)(b * NN + i0 + ii)) * CC + col] = (v0 + v1) + (v2 + v3);
    }
}

// ---------------------------------------------------------------------------
// Launch
// ---------------------------------------------------------------------------
extern "C" void kernel_launch(void* const* d_in, const int* in_sizes, int n_in,
                              void* d_out, int out_size)
{
    const float* h   = (const float*)d_in[0];
    const float* adj = (const float*)d_in[1];
    const float* W1a = (const float*)d_in[2];
    const float* W1b = (const float*)d_in[3];
    const float* b1  = (const float*)d_in[4];
    const float* W2  = (const float*)d_in[5];
    const float* b2  = (const float*)d_in[6];
    const float* Wc1 = (const float*)d_in[7];
    const float* bc1 = (const float*)d_in[8];
    const float* Wc2 = (const float*)d_in[9];
    const float* bc2 = (const float*)d_in[10];
    float* out = (float*)d_out;

    prep_kernel<<<321, 256>>>(h, W1a, W1b, b1, W2, b2, Wc1);
    main_kernel<<<BB * NN / 2, 256>>>(adj, bc1, Wc2, bc2, out);
}